// round 1
// baseline (speedup 1.0000x reference)
#include <cuda_runtime.h>

#define Bq 16
#define Sq 128
#define Dq 300
#define Oq 64
#define Eq 16
#define Tq 45
#define ROWS_TOT (Bq*Sq)   // 2048
#define WROW (Dq+Eq)       // 316

// Scratch (allocation-free rule: __device__ globals)
__device__ float g_hi[ROWS_TOT*Oq];
__device__ float g_hj[ROWS_TOT*Oq];
__device__ float g_ht[ROWS_TOT*Oq];
__device__ float g_U1[Tq*Oq];
__device__ float g_U2[Tq*Oq];
__device__ float g_dvec[Tq];
__device__ int   g_start[Bq];
__device__ int   g_end[Bq];

// ---------------------------------------------------------------------------
// K1: aspect span per batch (robust to bool stored as 1-byte or 4-byte),
//     plus U1/U2/dvec precompute (dep-type embedding folded through W1/W2).
// ---------------------------------------------------------------------------
__global__ void prep_kernel(const unsigned char* __restrict__ mask8,
                            const float* __restrict__ dep_table,
                            const float* __restrict__ W1,
                            const float* __restrict__ W2) {
    __shared__ int sfirst[Bq], slast[Bq], scnt[Bq];
    __shared__ int svalid;
    int tid = threadIdx.x;
    if (tid < Bq) { sfirst[tid] = Sq; slast[tid] = -1; scnt[tid] = 0; }
    __syncthreads();
    for (int i = tid; i < Bq*Sq; i += blockDim.x) {
        if (mask8[i]) {
            int b = i >> 7, p = i & 127;
            atomicMin(&sfirst[b], p);
            atomicMax(&slast[b], p);
            atomicAdd(&scnt[b], 1);
        }
    }
    __syncthreads();
    if (tid == 0) {
        int v = 1;
        for (int b = 0; b < Bq; b++)
            if (scnt[b] != 3 || slast[b] - sfirst[b] != 2) v = 0;
        svalid = v;
    }
    __syncthreads();
    if (!svalid) {
        // mask was serialized as 4-byte elements; reinterpret.
        if (tid < Bq) { sfirst[tid] = Sq; slast[tid] = -1; }
        __syncthreads();
        const int* mask32 = (const int*)mask8;
        for (int i = tid; i < Bq*Sq; i += blockDim.x) {
            if (mask32[i] != 0) {
                int b = i >> 7, p = i & 127;
                atomicMin(&sfirst[b], p);
                atomicMax(&slast[b], p);
            }
        }
        __syncthreads();
    }
    if (tid < Bq) { g_start[tid] = sfirst[tid]; g_end[tid] = slast[tid]; }

    // U1[ty][o] = sum_e W1[o, D+e] * dep_table[ty, e]   (same for U2)
    for (int idx = tid; idx < Tq*Oq; idx += blockDim.x) {
        int ty = idx >> 6, o = idx & 63;
        float s1 = 0.f, s2 = 0.f;
        #pragma unroll
        for (int e = 0; e < Eq; e++) {
            float de = dep_table[ty*Eq + e];
            s1 += W1[o*WROW + Dq + e] * de;
            s2 += W2[o*WROW + Dq + e] * de;
        }
        g_U1[idx] = s1;
        g_U2[idx] = s2;
    }
    __syncthreads();
    if (tid < Tq) {
        float s = 0.f;
        #pragma unroll 8
        for (int o = 0; o < Oq; o++) s += g_U1[tid*Oq + o] * g_U2[tid*Oq + o];
        g_dvec[tid] = s;
    }
}

// ---------------------------------------------------------------------------
// K2: position-weighted h, then fused triple GEMM:
//     hi = hw @ W1[:, :D]^T + b1 ; hj (W2) ; h_trans (Wg)
//     16 rows/block, 256 threads = (o:64, rowgroup:4), float4 inner loop.
// ---------------------------------------------------------------------------
__global__ void __launch_bounds__(256) gemm_kernel(
        const float* __restrict__ h,
        const float* __restrict__ W1, const float* __restrict__ b1,
        const float* __restrict__ W2, const float* __restrict__ b2,
        const float* __restrict__ Wg, const float* __restrict__ bg) {
    __shared__ float hw[16*Dq];
    __shared__ float sw[16];
    int tid = threadIdx.x;
    int row0 = blockIdx.x * 16;

    if (tid < 16) {
        int gr = row0 + tid, b = gr >> 7, s = gr & 127;
        int st = g_start[b], en = g_end[b];
        float w;
        if (s < st)      w = 1.0f - (float)(st - s) * (1.0f/128.0f);
        else if (s > en) w = 1.0f - (float)(s - en) * (1.0f/128.0f);
        else             w = 0.0f;
        sw[tid] = w;
    }
    __syncthreads();

    // Load 16 rows of h, apply position weight, vectorized (300 = 75 float4)
    const float4* h4 = (const float4*)h;
    float4* hw4 = (float4*)hw;
    for (int i = tid; i < 16*75; i += 256) {
        int r = i / 75, q = i - r*75;
        float4 v = h4[(size_t)(row0 + r)*75 + q];
        float w = sw[r];
        v.x *= w; v.y *= w; v.z *= w; v.w *= w;
        hw4[r*75 + q] = v;
    }
    __syncthreads();

    int o  = tid & 63;
    int rg = tid >> 6;
    const float4* W1_4 = (const float4*)(W1 + o*WROW);  // 316 % 4 == 0
    const float4* W2_4 = (const float4*)(W2 + o*WROW);
    const float4* Wg_4 = (const float4*)(Wg + o*Dq);    // 300 % 4 == 0
    const float4* hrow[4];
    #pragma unroll
    for (int j = 0; j < 4; j++) hrow[j] = (const float4*)(hw + (rg*4 + j)*Dq);

    float a1[4] = {0,0,0,0}, a2[4] = {0,0,0,0}, ag[4] = {0,0,0,0};
    #pragma unroll 5
    for (int d4 = 0; d4 < 75; d4++) {
        float4 w1 = __ldg(&W1_4[d4]);
        float4 w2 = __ldg(&W2_4[d4]);
        float4 wg = __ldg(&Wg_4[d4]);
        #pragma unroll
        for (int j = 0; j < 4; j++) {
            float4 hv = hrow[j][d4];                 // LDS.128 broadcast within warp
            a1[j] += hv.x*w1.x + hv.y*w1.y + hv.z*w1.z + hv.w*w1.w;
            a2[j] += hv.x*w2.x + hv.y*w2.y + hv.z*w2.z + hv.w*w2.w;
            ag[j] += hv.x*wg.x + hv.y*wg.y + hv.z*wg.z + hv.w*wg.w;
        }
    }
    float bb1 = b1[o], bb2 = b2[o], bbg = bg[o];
    #pragma unroll
    for (int j = 0; j < 4; j++) {
        int gr = row0 + rg*4 + j;
        g_hi[gr*Oq + o] = a1[j] + bb1;
        g_hj[gr*Oq + o] = a2[j] + bb2;
        g_ht[gr*Oq + o] = ag[j] + bbg;
    }
}

// ---------------------------------------------------------------------------
// K3: per (b,s): 45-entry score table, masked softmax, out = relu(A @ h_trans).
//     4 rows per block (same batch), 128 threads.
// ---------------------------------------------------------------------------
__global__ void __launch_bounds__(128) attn_kernel(
        const int* __restrict__ dep,
        const float* __restrict__ bias,
        float* __restrict__ out) {
    __shared__ float sU1[Tq*65], sU2[Tq*65];   // pad 65 -> conflict-free
    __shared__ float shi[Oq], shj[Oq];
    __shared__ float sval[Tq];
    __shared__ float sA[4*Sq];
    __shared__ float sred[4*Oq];
    __shared__ float sredw[4];
    __shared__ float sbcast;

    int tid = threadIdx.x;
    int gr0 = blockIdx.x * 4;
    int b = gr0 >> 7;

    for (int i = tid; i < Tq*Oq; i += 128) {
        int ty = i >> 6, k = i & 63;
        sU1[ty*65 + k] = g_U1[i];
        sU2[ty*65 + k] = g_U2[i];
    }
    __syncthreads();

    int lane = tid & 31, wid = tid >> 5;

    for (int r = 0; r < 4; r++) {
        int gr = gr0 + r;
        if (tid < Oq) { shi[tid] = g_hi[gr*Oq + tid]; shj[tid] = g_hj[gr*Oq + tid]; }
        __syncthreads();

        if (tid < Tq) {
            const float* u1 = &sU1[tid*65];
            const float* u2 = &sU2[tid*65];
            float acc = g_dvec[tid];
            #pragma unroll 8
            for (int k = 0; k < Oq; k++) {
                float hik = shi[k], hjk = shj[k];
                acc += hik*hjk + hik*u2[k] + u1[k]*hjk;
            }
            sval[tid] = acc * 0.125f;   // / sqrt(64)
        }
        __syncthreads();

        int ty = dep[gr*Sq + tid];
        float sc = sval[ty];

        // max over ALL 128 positions (reference maxes before masking)
        float m = sc;
        #pragma unroll
        for (int off = 16; off > 0; off >>= 1)
            m = fmaxf(m, __shfl_xor_sync(0xffffffffu, m, off));
        if (lane == 0) sredw[wid] = m;
        __syncthreads();
        if (tid == 0)
            sbcast = fmaxf(fmaxf(sredw[0], sredw[1]), fmaxf(sredw[2], sredw[3]));
        __syncthreads();
        float mx = sbcast;

        float e = (ty != 0) ? __expf(sc - mx) : 0.0f;
        float ssum = e;
        #pragma unroll
        for (int off = 16; off > 0; off >>= 1)
            ssum += __shfl_xor_sync(0xffffffffu, ssum, off);
        if (lane == 0) sredw[wid] = ssum;
        __syncthreads();
        if (tid == 0) sbcast = sredw[0] + sredw[1] + sredw[2] + sredw[3];
        __syncthreads();
        float tot = sbcast;

        sA[r*Sq + tid] = e / (tot + 1e-6f);
        __syncthreads();
    }

    // out[r][o] = relu( sum_t A[r][t] * h_trans[b][t][o] + bias[o] )
    int o = tid & 63, half = tid >> 6;
    float acc[4] = {0,0,0,0};
    const float* htb = g_ht + ((size_t)((b << 7) + half*64))*Oq + o;
    const float* Ab  = sA + half*64;
    #pragma unroll 4
    for (int u = 0; u < 64; u++) {
        float ht = htb[(size_t)u*Oq];
        #pragma unroll
        for (int r = 0; r < 4; r++) acc[r] += Ab[r*Sq + u] * ht;
    }
    if (half == 1) {
        #pragma unroll
        for (int r = 0; r < 4; r++) sred[r*Oq + o] = acc[r];
    }
    __syncthreads();
    if (half == 0) {
        float bo = bias[o];
        #pragma unroll
        for (int r = 0; r < 4; r++) {
            float v = acc[r] + sred[r*Oq + o] + bo;
            out[(size_t)(gr0 + r)*Oq + o] = fmaxf(v, 0.0f);
        }
    }
}

// ---------------------------------------------------------------------------
// Inputs (metadata order): h, dep_table, W1, b1, W2, b2, Wg, bg, bias,
//                          dep_type_matrix, aspect_mask
// ---------------------------------------------------------------------------
extern "C" void kernel_launch(void* const* d_in, const int* in_sizes, int n_in,
                              void* d_out, int out_size) {
    const float* h         = (const float*)d_in[0];
    const float* dep_table = (const float*)d_in[1];
    const float* W1        = (const float*)d_in[2];
    const float* b1        = (const float*)d_in[3];
    const float* W2        = (const float*)d_in[4];
    const float* b2        = (const float*)d_in[5];
    const float* Wg        = (const float*)d_in[6];
    const float* bg        = (const float*)d_in[7];
    const float* bias      = (const float*)d_in[8];
    const int*   dep       = (const int*)d_in[9];
    const unsigned char* mask = (const unsigned char*)d_in[10];

    prep_kernel<<<1, 256>>>(mask, dep_table, W1, W2);
    gemm_kernel<<<ROWS_TOT/16, 256>>>(h, W1, b1, W2, b2, Wg, bg);
    attn_kernel<<<ROWS_TOT/4, 128>>>(dep, bias, (float*)d_out);
}

// round 2
// speedup vs baseline: 1.6145x; 1.6145x over previous
#include <cuda_runtime.h>

#define Bq 16
#define Sq 128
#define Dq 300
#define Oq 64
#define Eq 16
#define Tq 45
#define ROWS_TOT (Bq*Sq)   // 2048
#define WROW (Dq+Eq)       // 316
#define KT 60              // K-chunk
#define PW 66              // padded transposed-W row (even for float2, 2-way store conflict only)

// Scratch (allocation-free rule: __device__ globals)
__device__ float g_hi[ROWS_TOT*Oq];
__device__ float g_hj[ROWS_TOT*Oq];
__device__ float g_ht[ROWS_TOT*Oq];
__device__ float g_U1[Tq*Oq];
__device__ float g_U2[Tq*Oq];

// ---------------------------------------------------------------------------
// K1 (gemm): per-block span scan + position-weighted triple GEMM
//   hi = hw @ W1[:, :D]^T + b1 ; hj (W2) ; h_trans (Wg)
//   16 rows/block, 256 threads, smem-staged transposed W chunks.
//   Blocks 0..44 additionally compute U1/U2 rows (dep-type fold through W1/W2).
// ---------------------------------------------------------------------------
__global__ void __launch_bounds__(256) gemm_kernel(
        const float* __restrict__ h,
        const float* __restrict__ W1, const float* __restrict__ b1,
        const float* __restrict__ W2, const float* __restrict__ b2,
        const float* __restrict__ Wg, const float* __restrict__ bg,
        const float* __restrict__ dep_table,
        const unsigned char* __restrict__ mask8) {
    extern __shared__ float sm[];
    float* sh  = sm;                       // 16*300 = 4800
    float* sW0 = sm + 16*Dq;               // KT*PW = 3960
    float* sW1s = sW0 + KT*PW;
    float* sW2s = sW1s + KT*PW;
    __shared__ int sp[5];                  // f8,l8,c8,f32,l32
    __shared__ float sw[16];

    int tid  = threadIdx.x;
    int row0 = blockIdx.x * 16;
    int b    = row0 >> 7;

    // ---- aspect span scan for this block's batch (dual-dtype robust) ----
    if (tid < 5) sp[tid] = (tid==0 || tid==3) ? Sq : ((tid==1 || tid==4) ? -1 : 0);
    __syncthreads();
    if (tid < 128 && mask8[(b<<7) + tid]) {
        atomicMin(&sp[0], tid); atomicMax(&sp[1], tid); atomicAdd(&sp[2], 1);
    }
    __syncthreads();
    bool valid8 = (sp[2] == 3 && sp[1] - sp[0] == 2);
    if (!valid8) {
        const int* m32 = (const int*)mask8;
        if (tid < 128 && m32[(b<<7) + tid] != 0) {
            atomicMin(&sp[3], tid); atomicMax(&sp[4], tid);
        }
    }
    __syncthreads();
    int st = valid8 ? sp[0] : sp[3];
    int en = valid8 ? sp[1] : sp[4];

    if (tid < 16) {
        int s = (row0 + tid) & 127;
        float w;
        if (s < st)      w = 1.0f - (float)(st - s) * (1.0f/128.0f);
        else if (s > en) w = 1.0f - (float)(s - en) * (1.0f/128.0f);
        else             w = 0.0f;
        sw[tid] = w;
    }
    __syncthreads();

    // ---- stage position-weighted h rows (16 x 300, float4) ----
    {
        const float4* h4 = (const float4*)(h + (size_t)row0 * Dq);
        float4* sh4 = (float4*)sh;
        for (int i = tid; i < 16*75; i += 256) {
            int r = i / 75;
            float4 v = h4[i];
            float w = sw[r];
            v.x *= w; v.y *= w; v.z *= w; v.w *= w;
            sh4[i] = v;
        }
    }

    // ---- main loop: 5 chunks of KT=60 ----
    int oi = (tid & 31) * 2;     // adjacent o pair
    int rg = tid >> 5;           // 0..7 -> rows rg*2, rg*2+1
    int r0 = rg * 2, r1 = r0 + 1;

    float a1x0=0,a1y0=0,a1x1=0,a1y1=0;   // W1: [row][o]
    float a2x0=0,a2y0=0,a2x1=0,a2y1=0;   // W2
    float agx0=0,agy0=0,agx1=0,agy1=0;   // Wg

    for (int c = 0; c < Dq/KT; c++) {
        __syncthreads();
        // stage W chunk transposed [k][o], pad PW: 3 mats x 64 o x 15 float4
        for (int i = tid; i < 3*64*15; i += 256) {
            int m = i / 960;
            int j = i - m * 960;
            int o = j / 15, q = j - o * 15;
            const float* Wsrc = (m == 0) ? W1 : (m == 1) ? W2 : Wg;
            int rowlen = (m == 2) ? Dq : WROW;
            float4 v = *(const float4*)(Wsrc + (size_t)o * rowlen + c*KT + q*4);
            float* dst = (m == 0) ? sW0 : (m == 1) ? sW1s : sW2s;
            int k = q * 4;
            dst[(k+0)*PW + o] = v.x;
            dst[(k+1)*PW + o] = v.y;
            dst[(k+2)*PW + o] = v.z;
            dst[(k+3)*PW + o] = v.w;
        }
        __syncthreads();

        const float* hr0 = sh + r0*Dq + c*KT;
        const float* hr1 = sh + r1*Dq + c*KT;
        #pragma unroll 6
        for (int k = 0; k < KT; k++) {
            float2 w1 = *(const float2*)&sW0 [k*PW + oi];
            float2 w2 = *(const float2*)&sW1s[k*PW + oi];
            float2 wg = *(const float2*)&sW2s[k*PW + oi];
            float ha = hr0[k], hb = hr1[k];
            a1x0 += ha*w1.x; a1y0 += ha*w1.y; a1x1 += hb*w1.x; a1y1 += hb*w1.y;
            a2x0 += ha*w2.x; a2y0 += ha*w2.y; a2x1 += hb*w2.x; a2y1 += hb*w2.y;
            agx0 += ha*wg.x; agy0 += ha*wg.y; agx1 += hb*wg.x; agy1 += hb*wg.y;
        }
    }

    // ---- epilogue ----
    float2 bb1 = *(const float2*)&b1[oi];
    float2 bb2 = *(const float2*)&b2[oi];
    float2 bbg = *(const float2*)&bg[oi];
    {
        size_t g0 = (size_t)(row0 + r0) * Oq + oi;
        size_t g1 = (size_t)(row0 + r1) * Oq + oi;
        *(float2*)&g_hi[g0] = make_float2(a1x0 + bb1.x, a1y0 + bb1.y);
        *(float2*)&g_hi[g1] = make_float2(a1x1 + bb1.x, a1y1 + bb1.y);
        *(float2*)&g_hj[g0] = make_float2(a2x0 + bb2.x, a2y0 + bb2.y);
        *(float2*)&g_hj[g1] = make_float2(a2x1 + bb2.x, a2y1 + bb2.y);
        *(float2*)&g_ht[g0] = make_float2(agx0 + bbg.x, agy0 + bbg.y);
        *(float2*)&g_ht[g1] = make_float2(agx1 + bbg.x, agy1 + bbg.y);
    }

    // ---- U1/U2 precompute: block ty < 45, tid < 64 (o) ----
    if (blockIdx.x < Tq && tid < Oq) {
        int ty = blockIdx.x;
        float s1 = 0.f, s2 = 0.f;
        #pragma unroll
        for (int e = 0; e < Eq; e++) {
            float de = __ldg(&dep_table[ty*Eq + e]);
            s1 += __ldg(&W1[tid*WROW + Dq + e]) * de;
            s2 += __ldg(&W2[tid*WROW + Dq + e]) * de;
        }
        g_U1[ty*Oq + tid] = s1;
        g_U2[ty*Oq + tid] = s2;
    }
}

// ---------------------------------------------------------------------------
// K2 (attn): per (b,s): 45-entry score table via (hi+U1)·(hj+U2) (dvec fused),
//   full-row max, masked softmax, out = relu(A @ h_trans). 4 rows/block.
// ---------------------------------------------------------------------------
__global__ void __launch_bounds__(128) attn_kernel(
        const int* __restrict__ dep,
        const float* __restrict__ bias,
        float* __restrict__ out) {
    __shared__ float sU1[Tq*65], sU2[Tq*65];
    __shared__ float shi4[4*Oq], shj4[4*Oq];
    __shared__ float sval[4*Tq];
    __shared__ float sA[4*Sq];
    __shared__ float sred[4*Oq];
    __shared__ float swr[4][4];      // [wid][r]
    __shared__ float sbmax[4], sbsum[4];

    int tid = threadIdx.x;
    int gr0 = blockIdx.x << 2;
    int b   = gr0 >> 7;

    for (int i = tid; i < Tq*Oq; i += 128) {
        int ty = i >> 6, k = i & 63;
        sU1[ty*65 + k] = g_U1[i];
        sU2[ty*65 + k] = g_U2[i];
    }
    for (int i = tid; i < 4*Oq; i += 128) {
        shi4[i] = g_hi[(size_t)gr0*Oq + i];
        shj4[i] = g_hj[(size_t)gr0*Oq + i];
    }
    __syncthreads();

    // score table: sval[r][ty] = 0.125 * sum_k (hi+U1)(hj+U2)
    for (int idx = tid; idx < 4*Tq; idx += 128) {
        int r = idx / Tq, ty = idx - r*Tq;
        const float* u1 = &sU1[ty*65];
        const float* u2 = &sU2[ty*65];
        const float* hi = &shi4[r*Oq];
        const float* hj = &shj4[r*Oq];
        float acc = 0.f;
        #pragma unroll 16
        for (int k = 0; k < Oq; k++)
            acc += (hi[k] + u1[k]) * (hj[k] + u2[k]);
        sval[r*Tq + ty] = acc * 0.125f;
    }
    __syncthreads();

    int lane = tid & 31, wid = tid >> 5;
    int tyv[4]; float sc[4];
    #pragma unroll
    for (int r = 0; r < 4; r++) {
        tyv[r] = dep[(size_t)(gr0 + r)*Sq + tid];
        sc[r]  = sval[r*Tq + tyv[r]];
    }
    // max over all 128 positions (reference maxes before masking)
    float mr[4] = {sc[0], sc[1], sc[2], sc[3]};
    #pragma unroll
    for (int off = 16; off; off >>= 1) {
        #pragma unroll
        for (int r = 0; r < 4; r++)
            mr[r] = fmaxf(mr[r], __shfl_xor_sync(0xffffffffu, mr[r], off));
    }
    if (lane == 0) {
        #pragma unroll
        for (int r = 0; r < 4; r++) swr[wid][r] = mr[r];
    }
    __syncthreads();
    if (tid < 4)
        sbmax[tid] = fmaxf(fmaxf(swr[0][tid], swr[1][tid]),
                           fmaxf(swr[2][tid], swr[3][tid]));
    __syncthreads();

    float er[4];
    #pragma unroll
    for (int r = 0; r < 4; r++)
        er[r] = (tyv[r] != 0) ? __expf(sc[r] - sbmax[r]) : 0.0f;
    float sr[4] = {er[0], er[1], er[2], er[3]};
    #pragma unroll
    for (int off = 16; off; off >>= 1) {
        #pragma unroll
        for (int r = 0; r < 4; r++)
            sr[r] += __shfl_xor_sync(0xffffffffu, sr[r], off);
    }
    if (lane == 0) {
        #pragma unroll
        for (int r = 0; r < 4; r++) swr[wid][r] = sr[r];
    }
    __syncthreads();
    if (tid < 4)
        sbsum[tid] = swr[0][tid] + swr[1][tid] + swr[2][tid] + swr[3][tid];
    __syncthreads();
    #pragma unroll
    for (int r = 0; r < 4; r++)
        sA[r*Sq + tid] = er[r] / (sbsum[r] + 1e-6f);
    __syncthreads();

    // out[r][o] = relu( sum_t A[r][t] * h_trans[b][t][o] + bias[o] )
    int o = tid & 63, half = tid >> 6;
    float acc[4] = {0, 0, 0, 0};
    const float* htb = g_ht + ((size_t)((b << 7) + half*64)) * Oq + o;
    const float* Ab  = sA + half*64;
    #pragma unroll 4
    for (int u = 0; u < 64; u++) {
        float htv = htb[(size_t)u * Oq];
        #pragma unroll
        for (int r = 0; r < 4; r++) acc[r] += Ab[r*Sq + u] * htv;
    }
    if (half == 1) {
        #pragma unroll
        for (int r = 0; r < 4; r++) sred[r*Oq + o] = acc[r];
    }
    __syncthreads();
    if (half == 0) {
        float bo = bias[o];
        #pragma unroll
        for (int r = 0; r < 4; r++) {
            float v = acc[r] + sred[r*Oq + o] + bo;
            out[(size_t)(gr0 + r)*Oq + o] = fmaxf(v, 0.0f);
        }
    }
}

// ---------------------------------------------------------------------------
// Inputs (metadata order): h, dep_table, W1, b1, W2, b2, Wg, bg, bias,
//                          dep_type_matrix, aspect_mask
// ---------------------------------------------------------------------------
extern "C" void kernel_launch(void* const* d_in, const int* in_sizes, int n_in,
                              void* d_out, int out_size) {
    const float* h         = (const float*)d_in[0];
    const float* dep_table = (const float*)d_in[1];
    const float* W1        = (const float*)d_in[2];
    const float* b1        = (const float*)d_in[3];
    const float* W2        = (const float*)d_in[4];
    const float* b2        = (const float*)d_in[5];
    const float* Wg        = (const float*)d_in[6];
    const float* bg        = (const float*)d_in[7];
    const float* bias      = (const float*)d_in[8];
    const int*   dep       = (const int*)d_in[9];
    const unsigned char* mask = (const unsigned char*)d_in[10];

    const int smem_bytes = (16*Dq + 3*KT*PW) * (int)sizeof(float);  // ~66.7 KB
    cudaFuncSetAttribute(gemm_kernel,
                         cudaFuncAttributeMaxDynamicSharedMemorySize, smem_bytes);

    gemm_kernel<<<ROWS_TOT/16, 256, smem_bytes>>>(h, W1, b1, W2, b2, Wg, bg,
                                                  dep_table, mask);
    attn_kernel<<<ROWS_TOT/4, 128>>>(dep, bias, (float*)d_out);
}